// round 2
// baseline (speedup 1.0000x reference)
#include <cuda_runtime.h>
#include <math.h>

// Problem constants
#define NTAU 64
#define NANG 64
#define KH_ 5
#define KW_ 5
#define OC_ 32
#define IC_ 8
#define NB 4
#define XY 256
#define NSAMP (NB * XY)          // 1024
#define HOUT 60
#define WOUT 64
#define WPEROC 200               // IC*KH*KW
#define WTOT (OC_ * WPEROC)      // 6400

// Conv kernel config
#define ROWS 72                  // padded smem row stride (floats)
#define TILE_FLOATS (IC_ * NTAU * ROWS)   // 36864
#define CONV_THREADS 512
#define NWARPS (CONV_THREADS / 32)        // 16
// tile + duplicated weight pairs (8B each) + partial val/idx arrays
#define SMEM_BYTES (TILE_FLOATS * 4 + WTOT * 8 + OC_ * NWARPS * 8)

typedef unsigned long long ull;

// Scratch (static device memory; no allocation APIs used)
__device__ float g_xt[(size_t)NSAMP * IC_ * NTAU * NANG];
__device__ float g_w[WTOT];
__device__ float g_val[NSAMP * OC_];
__device__ int   g_idx[NSAMP * OC_];

// ---------------- packed f32x2 helpers ----------------
__device__ __forceinline__ ull pk2(float lo, float hi) {
    ull r; asm("mov.b64 %0, {%1, %2};" : "=l"(r) : "f"(lo), "f"(hi)); return r;
}
__device__ __forceinline__ void upk2(ull v, float& lo, float& hi) {
    asm("mov.b64 {%0, %1}, %2;" : "=f"(lo), "=f"(hi) : "l"(v));
}
__device__ __forceinline__ void fma2(ull& acc, ull a, ull b) {
    asm("fma.rn.f32x2 %0, %1, %2, %0;" : "+l"(acc) : "l"(a), "l"(b));
}

// ---------------------------------------------------------------------------
// Weight normalization: w = g * v / ||v||_2 (per output channel)
// ---------------------------------------------------------------------------
__global__ void prep_weights(const float* __restrict__ v, const float* __restrict__ g) {
    __shared__ float scale[OC_];
    int tid = threadIdx.x;
    if (tid < OC_) {
        const float* p = v + tid * WPEROC;
        float s = 0.f;
        for (int k = 0; k < WPEROC; ++k) s += p[k] * p[k];
        scale[tid] = g[tid] / sqrtf(s);
    }
    __syncthreads();
    for (int i = tid; i < WTOT; i += blockDim.x)
        g_w[i] = v[i] * scale[i / WPEROC];
}

// ---------------------------------------------------------------------------
// Transpose (B,C,ta,xy) -> (n=b*256+xy, c, ta). Tiled 32x32 via smem.
// ---------------------------------------------------------------------------
__global__ void transpose_kernel(const float* __restrict__ x) {
    __shared__ float t[32][33];
    int bc  = blockIdx.z;            // b*8 + c
    int ta0 = blockIdx.x << 5;
    int xy0 = blockIdx.y << 5;
    int tx = threadIdx.x, ty = threadIdx.y;  // 32 x 8
    const float* src = x + (size_t)bc * 4096 * 256;
#pragma unroll
    for (int k = 0; k < 4; ++k)
        t[ty + k * 8][tx] = src[(size_t)(ta0 + ty + k * 8) * 256 + xy0 + tx];
    __syncthreads();
    int b = bc >> 3, c = bc & 7;
#pragma unroll
    for (int k = 0; k < 4; ++k) {
        int xy = xy0 + ty + k * 8;
        int ta = ta0 + tx;
        g_xt[((size_t)(b * XY + xy) * IC_ + c) * 4096 + ta] = t[tx][ty + k * 8];
    }
}

// ---------------------------------------------------------------------------
// Per-sample conv (circular in theta) + global max/argmax per oc.
// One block per sample. Inner math on packed fp32x2 (FFMA2) for 2x FMA pipe.
// ---------------------------------------------------------------------------
extern __shared__ float smem[];

__global__ void __launch_bounds__(CONV_THREADS, 1) conv_argmax_kernel() {
    float* tile = smem;                               // IC_*64*72 floats
    ull*   wsd  = (ull*)(smem + TILE_FLOATS);         // WTOT duplicated pairs
    float* pv   = (float*)(wsd + WTOT);               // OC_*NWARPS
    int*   pi   = (int*)(pv + OC_ * NWARPS);          // OC_*NWARPS

    int tid = threadIdx.x;
    int n = blockIdx.x;
    const float4* s4 = (const float4*)(g_xt + (size_t)n * (IC_ * NTAU * NANG));

    // Load tile (vectorized, coalesced gmem, conflict-free STS.128)
    for (int i = tid; i < IC_ * NTAU * (NANG / 4); i += CONV_THREADS) {
        int c = i >> 10, t = (i >> 4) & 63, a4 = i & 15;
        float4 vv = s4[i];
        *(float4*)&tile[c * (NTAU * ROWS) + t * ROWS + (a4 << 2)] = vv;
    }
    // Circular wrap: columns 64..67 = columns 0..3
    for (int i = tid; i < IC_ * NTAU; i += CONV_THREADS) {
        int c = i >> 6, t = i & 63;
        float4 vv = s4[i << 4];
        *(float4*)&tile[c * (NTAU * ROWS) + t * ROWS + 64] = vv;
    }
    // Duplicated weight pairs (w, w) for broadcast LDS.64
    for (int i = tid; i < WTOT; i += CONV_THREADS) {
        float w = g_w[i];
        wsd[i] = pk2(w, w);
    }
    __syncthreads();

    // 960 quads of 4 consecutive theta outputs; flat pos ascending
    int q0 = tid;
    int q1 = tid + CONV_THREADS;
    bool v1 = (q1 < 960);
    if (!v1) q1 = 0;
    int h0 = q0 >> 4, w0 = (q0 & 15) << 2;
    int h1 = q1 >> 4, w1 = (q1 & 15) << 2;

    int lane = tid & 31, warp = tid >> 5;
    const float* base0 = tile + h0 * ROWS + w0;
    const float* base1 = tile + h1 * ROWS + w1;

#pragma unroll 1
    for (int op = 0; op < OC_ / 2; ++op) {
        int oc0 = op * 2;
        const ull* wp0 = wsd + oc0 * WPEROC;
        const ull* wp1 = wp0 + WPEROC;

        // acc[oc 2][row 2][half 2] packed pairs
        ull a000 = 0, a001 = 0, a010 = 0, a011 = 0;
        ull a100 = 0, a101 = 0, a110 = 0, a111 = 0;

#pragma unroll 1
        for (int ic = 0; ic < IC_; ++ic) {
            const float* r0 = base0 + ic * (NTAU * ROWS);
            const float* r1 = base1 + ic * (NTAU * ROWS);
            const ull* wi0 = wp0 + ic * 25;
            const ull* wi1 = wp1 + ic * 25;
#pragma unroll
            for (int kh = 0; kh < KH_; ++kh) {
                // weight pairs (broadcast LDS.64)
                ull W0[KW_], W1[KW_];
#pragma unroll
                for (int kw = 0; kw < KW_; ++kw) {
                    W0[kw] = wi0[kh * 5 + kw];
                    W1[kw] = wi1[kh * 5 + kw];
                }
                // input pairs: even via LDS.64, odd via unpack+pack
                const ull* p0 = (const ull*)(r0 + kh * ROWS);
                const ull* p1 = (const ull*)(r1 + kh * ROWS);
                ull P0[7], P1[7];
                P0[0] = p0[0]; P0[2] = p0[1]; P0[4] = p0[2]; P0[6] = p0[3];
                P1[0] = p1[0]; P1[2] = p1[1]; P1[4] = p1[2]; P1[6] = p1[3];
                {
                    float x0l, x0h, x1l, x1h, x2l, x2h, x3l;
                    upk2(P0[0], x0l, x0h); upk2(P0[2], x1l, x1h);
                    upk2(P0[4], x2l, x2h); upk2(P0[6], x3l, x0l);
                    P0[1] = pk2(x0h, x1l); P0[3] = pk2(x1h, x2l); P0[5] = pk2(x2h, x3l);
                    (void)x3l;
                }
                {
                    float y0l, y0h, y1l, y1h, y2l, y2h, y3l;
                    upk2(P1[0], y0l, y0h); upk2(P1[2], y1l, y1h);
                    upk2(P1[4], y2l, y2h); upk2(P1[6], y3l, y0l);
                    P1[1] = pk2(y0h, y1l); P1[3] = pk2(y1h, y2l); P1[5] = pk2(y2h, y3l);
                    (void)y3l;
                }
#pragma unroll
                for (int kw = 0; kw < KW_; ++kw) {
                    fma2(a000, P0[kw],     W0[kw]);
                    fma2(a001, P0[kw + 2], W0[kw]);
                    fma2(a010, P1[kw],     W0[kw]);
                    fma2(a011, P1[kw + 2], W0[kw]);
                    fma2(a100, P0[kw],     W1[kw]);
                    fma2(a101, P0[kw + 2], W1[kw]);
                    fma2(a110, P1[kw],     W1[kw]);
                    fma2(a111, P1[kw + 2], W1[kw]);
                }
            }
        }

        // unpack accumulators -> per-output scalars
        float o0[2][4], o1[2][4];   // [oc][xq] for quad0 / quad1
        upk2(a000, o0[0][0], o0[0][1]); upk2(a001, o0[0][2], o0[0][3]);
        upk2(a100, o0[1][0], o0[1][1]); upk2(a101, o0[1][2], o0[1][3]);
        upk2(a010, o1[0][0], o1[0][1]); upk2(a011, o1[0][2], o1[0][3]);
        upk2(a110, o1[1][0], o1[1][1]); upk2(a111, o1[1][2], o1[1][3]);

        // max/argmax for the two ocs (first-occurrence semantics)
#pragma unroll
        for (int o = 0; o < 2; ++o) {
            float bv = -1e30f;
            int bi = 0x7FFFFFFF;
#pragma unroll
            for (int xq = 0; xq < 4; ++xq) {
                float val = o0[o][xq];
                int pos = h0 * 64 + w0 + xq;
                if (val > bv) { bv = val; bi = pos; }
            }
            if (v1) {
#pragma unroll
                for (int xq = 0; xq < 4; ++xq) {
                    float val = o1[o][xq];
                    int pos = h1 * 64 + w1 + xq;
                    if (val > bv) { bv = val; bi = pos; }
                }
            }
#pragma unroll
            for (int off = 16; off; off >>= 1) {
                float ov = __shfl_down_sync(0xffffffffu, bv, off);
                int   oi = __shfl_down_sync(0xffffffffu, bi, off);
                if (ov > bv || (ov == bv && oi < bi)) { bv = ov; bi = oi; }
            }
            if (lane == 0) {
                pv[(oc0 + o) * NWARPS + warp] = bv;
                pi[(oc0 + o) * NWARPS + warp] = bi;
            }
        }
    }
    __syncthreads();
    if (tid < OC_) {
        float bv = pv[tid * NWARPS];
        int   bi = pi[tid * NWARPS];
#pragma unroll
        for (int r = 1; r < NWARPS; ++r) {
            float ov = pv[tid * NWARPS + r];
            int   oi = pi[tid * NWARPS + r];
            if (ov > bv || (ov == bv && oi < bi)) { bv = ov; bi = oi; }
        }
        g_val[n * OC_ + tid] = bv;
        g_idx[n * OC_ + tid] = bi;
    }
}

// ---------------------------------------------------------------------------
// Softmax over spatial (256) per (b,oc) + tau/phase encoding.
// ---------------------------------------------------------------------------
__global__ void finalize_kernel(float* __restrict__ out) {
    int b = blockIdx.x, oc = blockIdx.y;
    int xy = threadIdx.x;
    int n = b * XY + xy;
    float v = g_val[n * OC_ + oc];
    int idx = g_idx[n * OC_ + oc];

    __shared__ float sm[8];
    __shared__ float s4[8][4];
    __shared__ float bc[5];
    int lane = xy & 31, warp = xy >> 5;

    float m = v;
#pragma unroll
    for (int off = 16; off; off >>= 1) m = fmaxf(m, __shfl_xor_sync(0xffffffffu, m, off));
    if (lane == 0) sm[warp] = m;
    __syncthreads();
    if (xy == 0) {
        float mm = sm[0];
#pragma unroll
        for (int r = 1; r < 8; ++r) mm = fmaxf(mm, sm[r]);
        bc[0] = mm;
    }
    __syncthreads();
    m = bc[0];

    float e = expf(v - m);
    float tau = (float)idx * (1.0f / 4096.0f);
    float phase = (float)(idx & 63) * 0.09817477042468103f;  // 2*pi/64
    float cp = cosf(phase), sp = sinf(phase);

    float se = e, st = e * tau, sc = e * cp, ss = e * sp;
#pragma unroll
    for (int off = 16; off; off >>= 1) {
        se += __shfl_xor_sync(0xffffffffu, se, off);
        st += __shfl_xor_sync(0xffffffffu, st, off);
        sc += __shfl_xor_sync(0xffffffffu, sc, off);
        ss += __shfl_xor_sync(0xffffffffu, ss, off);
    }
    if (lane == 0) { s4[warp][0] = se; s4[warp][1] = st; s4[warp][2] = sc; s4[warp][3] = ss; }
    __syncthreads();
    if (xy == 0) {
        float a = 0, b2 = 0, c = 0, d = 0;
#pragma unroll
        for (int r = 0; r < 8; ++r) { a += s4[r][0]; b2 += s4[r][1]; c += s4[r][2]; d += s4[r][3]; }
        bc[1] = a; bc[2] = b2; bc[3] = c; bc[4] = d;
    }
    __syncthreads();
    float Se = bc[1], St = bc[2], Sc = bc[3], Ss = bc[4];

    float rel = phase - atan2f(Ss, Sc);
    size_t base = (size_t)n * (4 * OC_) + oc;
    out[base]          = v;
    out[base + OC_]    = tau - St / Se;
    out[base + 2*OC_]  = cosf(rel);
    out[base + 3*OC_]  = sinf(rel);
}

// ---------------------------------------------------------------------------
extern "C" void kernel_launch(void* const* d_in, const int* in_sizes, int n_in,
                              void* d_out, int out_size) {
    const float* x = (const float*)d_in[0];       // (4,8,64,64,16,16)
    const float* v = (const float*)d_in[1];       // (32,8,5,5)
    const float* g = (const float*)d_in[2];       // (32,)
    float* out = (float*)d_out;                   // (4,16,16,128,1,1)

    cudaFuncSetAttribute(conv_argmax_kernel,
                         cudaFuncAttributeMaxDynamicSharedMemorySize, SMEM_BYTES);

    prep_weights<<<1, 256>>>(v, g);
    transpose_kernel<<<dim3(128, 8, 32), dim3(32, 8)>>>(x);
    conv_argmax_kernel<<<NSAMP, CONV_THREADS, SMEM_BYTES>>>();
    finalize_kernel<<<dim3(NB, OC_), 256>>>(out);
}